// round 1
// baseline (speedup 1.0000x reference)
#include <cuda_runtime.h>
#include <math.h>

#define NFACES 512
#define HW     256
#define NPIX   (HW*HW)
#define NTEX   (NFACES*4*4*4*3)   // 98304
#define NBLK   512                 // raster blocks
#define TPB    64                  // raster threads/block (2 px per thread)

// Scratch (no allocations allowed)
__device__ float g_faceData[NFACES * 16];
__device__ float g_tanhTex[NTEX];
__device__ float g_partials[NBLK];

// ---------------------------------------------------------------------------
// Kernel 1: per-face preprocessing (camera transform + edge coefficients)
// ---------------------------------------------------------------------------
__global__ void prep_faces(const float* __restrict__ verts,
                           const int*   __restrict__ faces) {
    int f = blockIdx.x * blockDim.x + threadIdx.x;
    if (f >= NFACES) return;

    // eye = [D*cos(0)*sin(pi/2), D*sin(0), -D*cos(0)*cos(pi/2)] computed in double -> f32
    const float ex = 2.732f, ey = 0.0f, ez = -1.6728675276352844e-16f;
    // look_at rotation (f32, mirrors reference formulas)
    float n  = sqrtf(ex*ex + ey*ey + ez*ez);
    float zx = -ex/n, zy = -ey/n, zz = -ez/n;
    // x = cross(up=(0,1,0), z) = (zz, 0, -zx)
    float xx = zz, xy = 0.f, xz = -zx;
    float xn = sqrtf(xx*xx + xy*xy + xz*xz);
    xx /= xn; xy /= xn; xz /= xn;
    // y = cross(z, x)
    float yx = zy*xz - zz*xy;
    float yy = zz*xx - zx*xz;
    float yz = zx*xy - zy*xx;

    int i0 = faces[3*f+0], i1 = faces[3*f+1], i2 = faces[3*f+2];

    float o[16];
    #pragma unroll
    for (int k = 0; k < 16; k++) o[k] = 0.f;

    float vx, vy, vz, tx, ty, tz;
    // vertex a
    vx = verts[3*i0+0]-ex; vy = verts[3*i0+1]-ey; vz = verts[3*i0+2]-ez;
    float ax = vx*xx+vy*xy+vz*xz, ay = vx*yx+vy*yy+vz*yz, az = vx*zx+vy*zy+vz*zz;
    // vertex b
    vx = verts[3*i1+0]-ex; vy = verts[3*i1+1]-ey; vz = verts[3*i1+2]-ez;
    float bx = vx*xx+vy*xy+vz*xz, by = vx*yx+vy*yy+vz*yz, bz = vx*zx+vy*zy+vz*zz;
    // vertex c
    vx = verts[3*i2+0]-ex; vy = verts[3*i2+1]-ey; vz = verts[3*i2+2]-ez;
    float cx = vx*xx+vy*xy+vz*xz, cy = vx*yx+vy*yy+vz*yz, cz = vx*zx+vy*zy+vz*zz;
    (void)tx; (void)ty; (void)tz;

    float denom = (bx-ax)*(cy-ay) - (by-ay)*(cx-ax);
    if (fabsf(denom) <= 1e-8f) {
        // degenerate: force u = -1 so inside test always fails
        o[2] = -1.f; o[5] = -1.f; o[8] = -1.f;    // C0, C1, C2
    } else {
        float s = (denom > 0.f) ? 1.f : -1.f;
        float r = 1.0f / fabsf(denom);
        // u_i = s*w_i as affine functions of pixel (Px,Py)
        o[0] = s*(by-cy);                              // A0
        o[1] = s*(cx-bx);                              // B0
        o[2] = s*((cy-by)*bx - (cx-bx)*by);            // C0
        o[3] = s*(cy-ay);                              // A1
        o[4] = s*(ax-cx);                              // B1
        o[5] = s*((ay-cy)*cx - (ax-cx)*cy);            // C1
        o[6] = s*(ay-by);                              // A2
        o[7] = s*(bx-ax);                              // B2
        o[8] = s*((by-ay)*ax - (bx-ax)*ay);            // C2
        o[9]  = az * r;                                // D0 (depth = u·D)
        o[10] = bz * r;                                // D1
        o[11] = cz * r;                                // D2
        o[12] = r;                                     // for barycentrics at lookup
    }
    float4* dst = reinterpret_cast<float4*>(&g_faceData[f*16]);
    dst[0] = make_float4(o[0], o[1], o[2],  o[3]);
    dst[1] = make_float4(o[4], o[5], o[6],  o[7]);
    dst[2] = make_float4(o[8], o[9], o[10], o[11]);
    dst[3] = make_float4(o[12], 0.f, 0.f, 0.f);
}

// ---------------------------------------------------------------------------
// Kernel 2: tanh of the whole texture (keeps tanh out of the hot pixel path)
// ---------------------------------------------------------------------------
__global__ void tanh_tex(const float* __restrict__ tex) {
    int i = blockIdx.x * blockDim.x + threadIdx.x;
    if (i < NTEX) g_tanhTex[i] = tanhf(tex[i]);
}

// ---------------------------------------------------------------------------
// Kernel 3: rasterize + shade + SSE partial per block
// ---------------------------------------------------------------------------
__device__ __forceinline__ float pixel_loss(int p, float px, float py, int bi,
                                            const float4* __restrict__ sF,
                                            const float*  __restrict__ ref) {
    float c0 = 0.f, c1 = 0.f, c2 = 0.f;
    if (bi >= 0) {
        float4 q0 = sF[bi*4+0];
        float4 q1 = sF[bi*4+1];
        float  C2 = sF[bi*4+2].x;
        float  r  = sF[bi*4+3].x;
        float u0 = fmaf(q0.x, px, fmaf(q0.y, py, q0.z));
        float u1 = fmaf(q0.w, px, fmaf(q1.x, py, q1.y));
        float u2 = fmaf(q1.z, px, fmaf(q1.w, py, C2));
        int t0 = (int)rintf(u0 * r * 3.0f);
        int t1 = (int)rintf(u1 * r * 3.0f);
        int t2 = (int)rintf(u2 * r * 3.0f);
        t0 = min(max(t0, 0), 3);
        t1 = min(max(t1, 0), 3);
        t2 = min(max(t2, 0), 3);
        int base = bi*192 + t0*48 + t1*12 + t2*3;
        c0 = g_tanhTex[base+0];
        c1 = g_tanhTex[base+1];
        c2 = g_tanhTex[base+2];
    }
    float r0 = ref[p], r1 = ref[p + NPIX], r2 = ref[p + 2*NPIX];
    float d0 = c0 - r0, d1 = c1 - r1, d2 = c2 - r2;
    return fmaf(d0, d0, fmaf(d1, d1, d2*d2));
}

__global__ void __launch_bounds__(TPB) raster(const float* __restrict__ ref) {
    __shared__ float4 sF[NFACES * 4];   // 32 KB

    const float4* gsrc = reinterpret_cast<const float4*>(g_faceData);
    for (int i = threadIdx.x; i < NFACES*4; i += TPB) sF[i] = gsrc[i];
    __syncthreads();

    int t  = blockIdx.x * TPB + threadIdx.x;   // 0..32767
    int p0 = t * 2;                             // two horizontally adjacent pixels
    int row = p0 >> 8;
    int col = p0 & 255;
    const float DX = 2.0f / 256.0f;
    float px = ((col + 0.5f) * (1.0f/256.0f)) * 2.0f - 1.0f;
    float py = 1.0f - ((row + 0.5f) * (1.0f/256.0f)) * 2.0f;

    float bd0 = __int_as_float(0x7f800000), bd1 = bd0;  // +inf
    int   bi0 = -1, bi1 = -1;

    #pragma unroll 4
    for (int f = 0; f < NFACES; f++) {
        float4 q0 = sF[f*4+0];
        float4 q1 = sF[f*4+1];
        float4 q2 = sF[f*4+2];
        // pixel 0
        float u0 = fmaf(q0.x, px, fmaf(q0.y, py, q0.z));
        float u1 = fmaf(q0.w, px, fmaf(q1.x, py, q1.y));
        float u2 = fmaf(q1.z, px, fmaf(q1.w, py, q2.x));
        float d0 = fmaf(u0, q2.y, fmaf(u1, q2.z, u2*q2.w));
        if (u0 >= 0.f && u1 >= 0.f && u2 >= 0.f && d0 > 0.f && d0 < bd0) {
            bd0 = d0; bi0 = f;
        }
        // pixel 1 (incremental: u += A*DX)
        float v0 = fmaf(q0.x, DX, u0);
        float v1 = fmaf(q0.w, DX, u1);
        float v2 = fmaf(q1.z, DX, u2);
        float d1 = fmaf(v0, q2.y, fmaf(v1, q2.z, v2*q2.w));
        if (v0 >= 0.f && v1 >= 0.f && v2 >= 0.f && d1 > 0.f && d1 < bd1) {
            bd1 = d1; bi1 = f;
        }
    }

    float acc = pixel_loss(p0,     px,      py, bi0, sF, ref)
              + pixel_loss(p0 + 1, px + DX, py, bi1, sF, ref);

    // deterministic block reduction (64 threads = 2 warps)
    #pragma unroll
    for (int o = 16; o > 0; o >>= 1)
        acc += __shfl_down_sync(0xFFFFFFFFu, acc, o);
    __shared__ float wsum[2];
    int lane = threadIdx.x & 31, wid = threadIdx.x >> 5;
    if (lane == 0) wsum[wid] = acc;
    __syncthreads();
    if (threadIdx.x == 0) g_partials[blockIdx.x] = wsum[0] + wsum[1];
}

// ---------------------------------------------------------------------------
// Kernel 4: deterministic final reduction
// ---------------------------------------------------------------------------
__global__ void finalize(float* __restrict__ out) {
    int tid = threadIdx.x;
    float v = g_partials[tid];
    #pragma unroll
    for (int o = 16; o > 0; o >>= 1)
        v += __shfl_down_sync(0xFFFFFFFFu, v, o);
    __shared__ float ws[16];
    if ((tid & 31) == 0) ws[tid >> 5] = v;
    __syncthreads();
    if (tid == 0) {
        float s = 0.f;
        #pragma unroll
        for (int w = 0; w < 16; w++) s += ws[w];
        out[0] = s;
    }
}

// ---------------------------------------------------------------------------
extern "C" void kernel_launch(void* const* d_in, const int* in_sizes, int n_in,
                              void* d_out, int out_size) {
    // identify inputs by element count (robust to ordering)
    const float* verts = nullptr;   // 1*642*3   = 1926
    const float* tex   = nullptr;   // 1*512*64*3= 98304
    const float* ref   = nullptr;   // 1*3*256^2 = 196608
    const int*   faces = nullptr;   // 1*512*3   = 1536
    for (int i = 0; i < n_in; i++) {
        switch (in_sizes[i]) {
            case 1926:   verts = (const float*)d_in[i]; break;
            case 98304:  tex   = (const float*)d_in[i]; break;
            case 196608: ref   = (const float*)d_in[i]; break;
            case 1536:   faces = (const int*)  d_in[i]; break;
            default: break;
        }
    }

    prep_faces<<<1, NFACES>>>(verts, faces);
    tanh_tex<<<(NTEX + 255)/256, 256>>>(tex);
    raster<<<NBLK, TPB>>>(ref);
    finalize<<<1, NBLK>>>((float*)d_out);
}

// round 2
// speedup vs baseline: 1.4700x; 1.4700x over previous
#include <cuda_runtime.h>
#include <math.h>

#define NFACES 512
#define HW     256
#define NPIX   (HW*HW)
#define NTEX   (NFACES*64*3)      // 98304
#define RBLK   256                // raster blocks (16x16 tiles)
#define RTPB   128                // raster threads/block (2 px each)

__device__ float4 g_bbox[NFACES];         // xmin, xmax, ymin, ymax
__device__ float4 g_face[NFACES*4];       // q0,q1,q2,(r,-,-,-)
__device__ float  g_tanhTex[NTEX];
__device__ float  g_partials[RBLK];
__device__ unsigned int g_counter;

// ---------------------------------------------------------------------------
// Kernel A: fused per-face prep (blocks 0-1) + texture tanh (blocks 2..97)
// ---------------------------------------------------------------------------
__global__ void __launch_bounds__(256) prep_and_tanh(const float* __restrict__ verts,
                                                     const int*   __restrict__ faces,
                                                     const float* __restrict__ tex) {
    int b = blockIdx.x;
    if (b >= 2) {
        // tanh over texture, float4-vectorized: 24576 float4s over 96 blocks
        int i = (b - 2) * 256 + threadIdx.x;
        float4 v = __ldg(reinterpret_cast<const float4*>(tex) + i);
        v.x = tanhf(v.x); v.y = tanhf(v.y); v.z = tanhf(v.z); v.w = tanhf(v.w);
        reinterpret_cast<float4*>(g_tanhTex)[i] = v;
        return;
    }
    if (b == 0 && threadIdx.x == 0) g_counter = 0;

    int f = b * 256 + threadIdx.x;   // 0..511

    const float ex = 2.732f, ey = 0.0f, ez = -1.6728675276352844e-16f;
    float n  = sqrtf(ex*ex + ey*ey + ez*ez);
    float zx = -ex/n, zy = -ey/n, zz = -ez/n;
    float xx = zz, xy = 0.f, xz = -zx;
    float xn = sqrtf(xx*xx + xy*xy + xz*xz);
    xx /= xn; xy /= xn; xz /= xn;
    float yx = zy*xz - zz*xy;
    float yy = zz*xx - zx*xz;
    float yz = zx*xy - zy*xx;

    int i0 = faces[3*f+0], i1 = faces[3*f+1], i2 = faces[3*f+2];

    float vx, vy, vz;
    vx = verts[3*i0+0]-ex; vy = verts[3*i0+1]-ey; vz = verts[3*i0+2]-ez;
    float ax = vx*xx+vy*xy+vz*xz, ay = vx*yx+vy*yy+vz*yz, az = vx*zx+vy*zy+vz*zz;
    vx = verts[3*i1+0]-ex; vy = verts[3*i1+1]-ey; vz = verts[3*i1+2]-ez;
    float bx = vx*xx+vy*xy+vz*xz, by = vx*yx+vy*yy+vz*yz, bz = vx*zx+vy*zy+vz*zz;
    vx = verts[3*i2+0]-ex; vy = verts[3*i2+1]-ey; vz = verts[3*i2+2]-ez;
    float cx = vx*xx+vy*xy+vz*xz, cy = vx*yx+vy*yy+vz*yz, cz = vx*zx+vy*zy+vz*zz;

    float denom = (bx-ax)*(cy-ay) - (by-ay)*(cx-ax);
    float o[13];
    float4 bbox;
    if (fabsf(denom) <= 1e-8f) {
        #pragma unroll
        for (int k = 0; k < 13; k++) o[k] = 0.f;
        o[2] = -1.f; o[5] = -1.f; o[8] = -1.f;
        bbox = make_float4(2.f, -2.f, 2.f, -2.f);   // empty -> always culled
    } else {
        float s = (denom > 0.f) ? 1.f : -1.f;
        float r = 1.0f / fabsf(denom);
        o[0] = s*(by-cy);
        o[1] = s*(cx-bx);
        o[2] = s*((cy-by)*bx - (cx-bx)*by);
        o[3] = s*(cy-ay);
        o[4] = s*(ax-cx);
        o[5] = s*((ay-cy)*cx - (ax-cx)*cy);
        o[6] = s*(ay-by);
        o[7] = s*(bx-ax);
        o[8] = s*((by-ay)*ax - (bx-ax)*ay);
        o[9]  = az * r;
        o[10] = bz * r;
        o[11] = cz * r;
        o[12] = r;
        float xmn = fminf(ax, fminf(bx, cx)) - 1e-6f;
        float xmx = fmaxf(ax, fmaxf(bx, cx)) + 1e-6f;
        float ymn = fminf(ay, fminf(by, cy)) - 1e-6f;
        float ymx = fmaxf(ay, fmaxf(by, cy)) + 1e-6f;
        bbox = make_float4(xmn, xmx, ymn, ymx);
    }
    g_bbox[f] = bbox;
    float4* dst = &g_face[f*4];
    dst[0] = make_float4(o[0], o[1], o[2],  o[3]);
    dst[1] = make_float4(o[4], o[5], o[6],  o[7]);
    dst[2] = make_float4(o[8], o[9], o[10], o[11]);
    dst[3] = make_float4(o[12], 0.f, 0.f, 0.f);
}

// ---------------------------------------------------------------------------
// Kernel B: tiled raster + shade + SSE, with fused deterministic finalize
// ---------------------------------------------------------------------------
__device__ __forceinline__ float pixel_loss(int p, float px, float py, int li,
                                            const float4* __restrict__ sQ,
                                            const short*  __restrict__ sList,
                                            const float*  __restrict__ ref) {
    float c0 = 0.f, c1 = 0.f, c2 = 0.f;
    if (li >= 0) {
        int f = sList[li];
        float4 q0 = sQ[li*3+0];
        float4 q1 = sQ[li*3+1];
        float  C2 = sQ[li*3+2].x;
        float  r  = __ldg(&g_face[f*4+3]).x;
        float u0 = fmaf(q0.x, px, fmaf(q0.y, py, q0.z));
        float u1 = fmaf(q0.w, px, fmaf(q1.x, py, q1.y));
        float u2 = fmaf(q1.z, px, fmaf(q1.w, py, C2));
        int t0 = (int)rintf(u0 * r * 3.0f);
        int t1 = (int)rintf(u1 * r * 3.0f);
        int t2 = (int)rintf(u2 * r * 3.0f);
        t0 = min(max(t0, 0), 3);
        t1 = min(max(t1, 0), 3);
        t2 = min(max(t2, 0), 3);
        int base = f*192 + t0*48 + t1*12 + t2*3;
        c0 = g_tanhTex[base+0];
        c1 = g_tanhTex[base+1];
        c2 = g_tanhTex[base+2];
    }
    float d0 = c0 - __ldg(ref + p);
    float d1 = c1 - __ldg(ref + p + NPIX);
    float d2 = c2 - __ldg(ref + p + 2*NPIX);
    return fmaf(d0, d0, fmaf(d1, d1, d2*d2));
}

__global__ void __launch_bounds__(RTPB) raster(const float* __restrict__ ref,
                                               float* __restrict__ out) {
    __shared__ float4 sQ[NFACES*3];      // staged survivor coefficients (<=24KB)
    __shared__ short  sList[NFACES];
    __shared__ int    sWarpCnt[4];
    __shared__ int    sCnt;
    __shared__ float  sWsum[4];

    const int tid  = threadIdx.x;
    const int lane = tid & 31, w = tid >> 5;

    // 16x16 tile
    const int tileX = blockIdx.x & 15, tileY = blockIdx.x >> 4;
    const int c0 = tileX * 16, r0 = tileY * 16;
    const float SC = 2.0f / 256.0f;
    const float tXmin = (c0 + 0.5f)  * SC - 1.0f;
    const float tXmax = (c0 + 15.5f) * SC - 1.0f;
    const float tYmax = 1.0f - (r0 + 0.5f)  * SC;
    const float tYmin = 1.0f - (r0 + 15.5f) * SC;

    if (tid == 0) sCnt = 0;
    __syncthreads();

    // ---- Phase 1: bbox cull + ballot compaction ----
    #pragma unroll
    for (int base = 0; base < NFACES; base += RTPB) {
        int f = base + tid;
        float4 bb = __ldg(&g_bbox[f]);
        bool ov = (bb.x <= tXmax) & (bb.y >= tXmin) & (bb.z <= tYmax) & (bb.w >= tYmin);
        unsigned m = __ballot_sync(0xFFFFFFFFu, ov);
        if (lane == 0) sWarpCnt[w] = __popc(m);
        __syncthreads();
        int off = sCnt;
        #pragma unroll
        for (int i = 0; i < 4; i++) if (i < w) off += sWarpCnt[i];
        if (ov) sList[off + __popc(m & ((1u << lane) - 1u))] = (short)f;
        __syncthreads();
        if (tid == 0) sCnt += sWarpCnt[0] + sWarpCnt[1] + sWarpCnt[2] + sWarpCnt[3];
        __syncthreads();
    }
    const int nf = sCnt;

    // ---- Stage survivor coefficients into SMEM ----
    for (int i = tid; i < nf * 3; i += RTPB) {
        int li = i / 3, c = i - li * 3;
        sQ[i] = __ldg(&g_face[(int)sList[li] * 4 + c]);
    }
    __syncthreads();

    // ---- Phase 2: per-pixel loop over survivors (2 px per thread) ----
    const int col = c0 + ((tid & 7) << 1);
    const int row = r0 + (tid >> 3);
    const float DX = SC;
    const float px = (col + 0.5f) * SC - 1.0f;
    const float py = 1.0f - (row + 0.5f) * SC;

    float bd0 = __int_as_float(0x7f800000), bd1 = bd0;
    int   li0 = -1, li1 = -1;

    #pragma unroll 2
    for (int i = 0; i < nf; i++) {
        float4 q0 = sQ[i*3+0];
        float4 q1 = sQ[i*3+1];
        float4 q2 = sQ[i*3+2];
        float u0 = fmaf(q0.x, px, fmaf(q0.y, py, q0.z));
        float u1 = fmaf(q0.w, px, fmaf(q1.x, py, q1.y));
        float u2 = fmaf(q1.z, px, fmaf(q1.w, py, q2.x));
        float d0 = fmaf(u0, q2.y, fmaf(u1, q2.z, u2*q2.w));
        if (u0 >= 0.f && u1 >= 0.f && u2 >= 0.f && d0 > 0.f && d0 < bd0) {
            bd0 = d0; li0 = i;
        }
        float v0 = fmaf(q0.x, DX, u0);
        float v1 = fmaf(q0.w, DX, u1);
        float v2 = fmaf(q1.z, DX, u2);
        float d1 = fmaf(v0, q2.y, fmaf(v1, q2.z, v2*q2.w));
        if (v0 >= 0.f && v1 >= 0.f && v2 >= 0.f && d1 > 0.f && d1 < bd1) {
            bd1 = d1; li1 = i;
        }
    }

    const int p0 = row * HW + col;
    float acc = pixel_loss(p0,     px,      py, li0, sQ, sList, ref)
              + pixel_loss(p0 + 1, px + DX, py, li1, sQ, sList, ref);

    // ---- block reduction ----
    #pragma unroll
    for (int o = 16; o > 0; o >>= 1)
        acc += __shfl_down_sync(0xFFFFFFFFu, acc, o);
    if (lane == 0) sWsum[w] = acc;
    __syncthreads();

    // ---- fused deterministic finalize (last block reduces fixed order) ----
    __shared__ bool sLast;
    if (tid == 0) {
        g_partials[blockIdx.x] = sWsum[0] + sWsum[1] + sWsum[2] + sWsum[3];
        __threadfence();
        unsigned t = atomicInc(&g_counter, 0xFFFFFFFFu);
        sLast = (t == RBLK - 1);
    }
    __syncthreads();
    if (sLast) {
        float v = __ldcg(&g_partials[tid]) + __ldcg(&g_partials[tid + RTPB]);
        #pragma unroll
        for (int o = 16; o > 0; o >>= 1)
            v += __shfl_down_sync(0xFFFFFFFFu, v, o);
        if (lane == 0) sWsum[w] = v;
        __syncthreads();
        if (tid == 0) out[0] = sWsum[0] + sWsum[1] + sWsum[2] + sWsum[3];
    }
}

// ---------------------------------------------------------------------------
extern "C" void kernel_launch(void* const* d_in, const int* in_sizes, int n_in,
                              void* d_out, int out_size) {
    const float* verts = nullptr;
    const float* tex   = nullptr;
    const float* ref   = nullptr;
    const int*   faces = nullptr;
    for (int i = 0; i < n_in; i++) {
        switch (in_sizes[i]) {
            case 1926:   verts = (const float*)d_in[i]; break;
            case 98304:  tex   = (const float*)d_in[i]; break;
            case 196608: ref   = (const float*)d_in[i]; break;
            case 1536:   faces = (const int*)  d_in[i]; break;
            default: break;
        }
    }
    prep_and_tanh<<<98, 256>>>(verts, faces, tex);
    raster<<<RBLK, RTPB>>>(ref, (float*)d_out);
}

// round 3
// speedup vs baseline: 1.6869x; 1.1476x over previous
#include <cuda_runtime.h>
#include <math.h>

#define NFACES 512
#define HW     256
#define NPIX   (HW*HW)
#define NTEX   (NFACES*64*3)      // 98304
#define RBLK   256                // raster blocks (16x16 tiles)
#define RTPB   256                // 8 warps: two face-groups of 4 warps

__device__ float4 g_bbox[NFACES];
__device__ float4 g_face[NFACES*4];
__device__ float  g_tanhTex[NTEX];
__device__ float  g_partials[RBLK];
__device__ unsigned int g_counter;

// ---------------------------------------------------------------------------
// Kernel A: fused per-face prep (blocks 0-1) + texture tanh (blocks 2..97)
// ---------------------------------------------------------------------------
__global__ void __launch_bounds__(256) prep_and_tanh(const float* __restrict__ verts,
                                                     const int*   __restrict__ faces,
                                                     const float* __restrict__ tex) {
    int b = blockIdx.x;
    if (b >= 2) {
        int i = (b - 2) * 256 + threadIdx.x;
        float4 v = __ldg(reinterpret_cast<const float4*>(tex) + i);
        v.x = tanhf(v.x); v.y = tanhf(v.y); v.z = tanhf(v.z); v.w = tanhf(v.w);
        reinterpret_cast<float4*>(g_tanhTex)[i] = v;
        return;
    }
    if (b == 0 && threadIdx.x == 0) g_counter = 0;

    int f = b * 256 + threadIdx.x;

    const float ex = 2.732f, ey = 0.0f, ez = -1.6728675276352844e-16f;
    float n  = sqrtf(ex*ex + ey*ey + ez*ez);
    float zx = -ex/n, zy = -ey/n, zz = -ez/n;
    float xx = zz, xy = 0.f, xz = -zx;
    float xn = sqrtf(xx*xx + xy*xy + xz*xz);
    xx /= xn; xy /= xn; xz /= xn;
    float yx = zy*xz - zz*xy;
    float yy = zz*xx - zx*xz;
    float yz = zx*xy - zy*xx;

    int i0 = faces[3*f+0], i1 = faces[3*f+1], i2 = faces[3*f+2];

    float vx, vy, vz;
    vx = verts[3*i0+0]-ex; vy = verts[3*i0+1]-ey; vz = verts[3*i0+2]-ez;
    float ax = vx*xx+vy*xy+vz*xz, ay = vx*yx+vy*yy+vz*yz, az = vx*zx+vy*zy+vz*zz;
    vx = verts[3*i1+0]-ex; vy = verts[3*i1+1]-ey; vz = verts[3*i1+2]-ez;
    float bx = vx*xx+vy*xy+vz*xz, by = vx*yx+vy*yy+vz*yz, bz = vx*zx+vy*zy+vz*zz;
    vx = verts[3*i2+0]-ex; vy = verts[3*i2+1]-ey; vz = verts[3*i2+2]-ez;
    float cx = vx*xx+vy*xy+vz*xz, cy = vx*yx+vy*yy+vz*yz, cz = vx*zx+vy*zy+vz*zz;

    float denom = (bx-ax)*(cy-ay) - (by-ay)*(cx-ax);
    float o[13];
    float4 bbox;
    if (fabsf(denom) <= 1e-8f) {
        #pragma unroll
        for (int k = 0; k < 13; k++) o[k] = 0.f;
        o[2] = -1.f; o[5] = -1.f; o[8] = -1.f;
        bbox = make_float4(2.f, -2.f, 2.f, -2.f);   // empty -> always culled
    } else {
        float s = (denom > 0.f) ? 1.f : -1.f;
        float r = 1.0f / fabsf(denom);
        o[0] = s*(by-cy);
        o[1] = s*(cx-bx);
        o[2] = s*((cy-by)*bx - (cx-bx)*by);
        o[3] = s*(cy-ay);
        o[4] = s*(ax-cx);
        o[5] = s*((ay-cy)*cx - (ax-cx)*cy);
        o[6] = s*(ay-by);
        o[7] = s*(bx-ax);
        o[8] = s*((by-ay)*ax - (bx-ax)*ay);
        o[9]  = az * r;
        o[10] = bz * r;
        o[11] = cz * r;
        o[12] = r;
        float xmn = fminf(ax, fminf(bx, cx)) - 1e-6f;
        float xmx = fmaxf(ax, fmaxf(bx, cx)) + 1e-6f;
        float ymn = fminf(ay, fminf(by, cy)) - 1e-6f;
        float ymx = fmaxf(ay, fmaxf(by, cy)) + 1e-6f;
        bbox = make_float4(xmn, xmx, ymn, ymx);
    }
    g_bbox[f] = bbox;
    float4* dst = &g_face[f*4];
    dst[0] = make_float4(o[0], o[1], o[2],  o[3]);
    dst[1] = make_float4(o[4], o[5], o[6],  o[7]);
    dst[2] = make_float4(o[8], o[9], o[10], o[11]);
    dst[3] = make_float4(o[12], 0.f, 0.f, 0.f);
}

// ---------------------------------------------------------------------------
// Kernel B: tiled raster, face list split across two warp-groups
// ---------------------------------------------------------------------------
__global__ void __launch_bounds__(RTPB) raster(const float* __restrict__ ref,
                                               float* __restrict__ out) {
    __shared__ float4 sQ[NFACES*3];        // 24 KB survivor coefficients
    __shared__ short  sList[NFACES];
    __shared__ int    sWarpCnt[8];
    __shared__ int    sCnt;
    __shared__ float  sBdA[256], sBdB[256];
    __shared__ short  sLiA[256], sLiB[256];
    __shared__ float  sWsum[8];

    const int tid  = threadIdx.x;
    const int lane = tid & 31, w = tid >> 5;

    const int tileX = blockIdx.x & 15, tileY = blockIdx.x >> 4;
    const int c0 = tileX * 16, r0 = tileY * 16;
    const float SC = 2.0f / 256.0f;
    const float tXmin = (c0 + 0.5f)  * SC - 1.0f;
    const float tXmax = (c0 + 15.5f) * SC - 1.0f;
    const float tYmax = 1.0f - (r0 + 0.5f)  * SC;
    const float tYmin = 1.0f - (r0 + 15.5f) * SC;

    if (tid == 0) sCnt = 0;
    __syncthreads();

    // ---- Phase 1: bbox cull + ballot compaction (2 rounds of 256) ----
    #pragma unroll
    for (int base = 0; base < NFACES; base += RTPB) {
        int f = base + tid;
        float4 bb = __ldg(&g_bbox[f]);
        bool ov = (bb.x <= tXmax) & (bb.y >= tXmin) & (bb.z <= tYmax) & (bb.w >= tYmin);
        unsigned m = __ballot_sync(0xFFFFFFFFu, ov);
        if (lane == 0) sWarpCnt[w] = __popc(m);
        __syncthreads();
        int off = sCnt;
        #pragma unroll
        for (int i = 0; i < 8; i++) if (i < w) off += sWarpCnt[i];
        if (ov) sList[off + __popc(m & ((1u << lane) - 1u))] = (short)f;
        __syncthreads();
        if (tid == 0) {
            int s = 0;
            #pragma unroll
            for (int i = 0; i < 8; i++) s += sWarpCnt[i];
            sCnt += s;
        }
        __syncthreads();
    }
    const int nf = sCnt;
    const int half = (nf + 1) >> 1;

    // ---- Stage survivor coefficients ----
    for (int i = tid; i < nf * 3; i += RTPB) {
        int li = i / 3, c = i - li * 3;
        sQ[i] = __ldg(&g_face[(int)sList[li] * 4 + c]);
    }
    __syncthreads();

    // ---- Phase 2: each warp-group tests half the faces for all 256 px ----
    const int group = tid >> 7;              // 0 or 1
    const int slot0 = (tid & 127) * 2;       // first of 2 horizontal pixels
    const float DX = SC;
    const float px = (c0 + (slot0 & 15) + 0.5f) * SC - 1.0f;
    const float py = 1.0f - (r0 + (slot0 >> 4) + 0.5f) * SC;

    const int fBeg = group ? half : 0;
    const int fEnd = group ? nf   : half;

    float bd0 = __int_as_float(0x7f800000), bd1 = bd0;
    int   li0 = -1, li1 = -1;

    #pragma unroll 2
    for (int i = fBeg; i < fEnd; i++) {
        float4 q0 = sQ[i*3+0];
        float4 q1 = sQ[i*3+1];
        float4 q2 = sQ[i*3+2];
        float u0 = fmaf(q0.x, px, fmaf(q0.y, py, q0.z));
        float u1 = fmaf(q0.w, px, fmaf(q1.x, py, q1.y));
        float u2 = fmaf(q1.z, px, fmaf(q1.w, py, q2.x));
        float d0 = fmaf(u0, q2.y, fmaf(u1, q2.z, u2*q2.w));
        float m0 = fminf(u0, fminf(u1, u2));
        if (m0 >= 0.f && d0 > 0.f && d0 < bd0) { bd0 = d0; li0 = i; }
        float v0 = fmaf(q0.x, DX, u0);
        float v1 = fmaf(q0.w, DX, u1);
        float v2 = fmaf(q1.z, DX, u2);
        float d1 = fmaf(v0, q2.y, fmaf(v1, q2.z, v2*q2.w));
        float m1 = fminf(v0, fminf(v1, v2));
        if (m1 >= 0.f && d1 > 0.f && d1 < bd1) { bd1 = d1; li1 = i; }
    }

    if (group == 0) {
        sBdA[slot0] = bd0; sLiA[slot0] = (short)li0;
        sBdA[slot0+1] = bd1; sLiA[slot0+1] = (short)li1;
    } else {
        sBdB[slot0] = bd0; sLiB[slot0] = (short)li0;
        sBdB[slot0+1] = bd1; sLiB[slot0+1] = (short)li1;
    }
    __syncthreads();

    // ---- Epilogue: 1 px/thread; merge candidates (tie -> group A = lower idx)
    const int colIn = tid & 15, rowIn = tid >> 4;
    const float qx = (c0 + colIn + 0.5f) * SC - 1.0f;
    const float qy = 1.0f - (r0 + rowIn + 0.5f) * SC;
    const int   p  = (r0 + rowIn) * HW + (c0 + colIn);

    float da = sBdA[tid], db = sBdB[tid];
    int li = (db < da) ? (int)sLiB[tid] : (int)sLiA[tid];

    float cc0 = 0.f, cc1 = 0.f, cc2 = 0.f;
    if (li >= 0) {
        int f = sList[li];
        float4 q0 = sQ[li*3+0];
        float4 q1 = sQ[li*3+1];
        float  C2 = sQ[li*3+2].x;
        float  r  = __ldg(&g_face[f*4+3]).x;
        float u0 = fmaf(q0.x, qx, fmaf(q0.y, qy, q0.z));
        float u1 = fmaf(q0.w, qx, fmaf(q1.x, qy, q1.y));
        float u2 = fmaf(q1.z, qx, fmaf(q1.w, qy, C2));
        int t0 = min(max((int)rintf(u0 * r * 3.0f), 0), 3);
        int t1 = min(max((int)rintf(u1 * r * 3.0f), 0), 3);
        int t2 = min(max((int)rintf(u2 * r * 3.0f), 0), 3);
        int base = f*192 + t0*48 + t1*12 + t2*3;
        cc0 = g_tanhTex[base+0];
        cc1 = g_tanhTex[base+1];
        cc2 = g_tanhTex[base+2];
    }
    float e0 = cc0 - __ldg(ref + p);
    float e1 = cc1 - __ldg(ref + p + NPIX);
    float e2 = cc2 - __ldg(ref + p + 2*NPIX);
    float acc = fmaf(e0, e0, fmaf(e1, e1, e2*e2));

    // ---- block reduction (8 warps) ----
    #pragma unroll
    for (int o = 16; o > 0; o >>= 1)
        acc += __shfl_down_sync(0xFFFFFFFFu, acc, o);
    if (lane == 0) sWsum[w] = acc;
    __syncthreads();

    // ---- fused deterministic finalize ----
    __shared__ bool sLast;
    if (tid == 0) {
        float s = 0.f;
        #pragma unroll
        for (int i = 0; i < 8; i++) s += sWsum[i];
        g_partials[blockIdx.x] = s;
        __threadfence();
        unsigned t = atomicInc(&g_counter, 0xFFFFFFFFu);
        sLast = (t == RBLK - 1);
    }
    __syncthreads();
    if (sLast) {
        float v = __ldcg(&g_partials[tid]);
        #pragma unroll
        for (int o = 16; o > 0; o >>= 1)
            v += __shfl_down_sync(0xFFFFFFFFu, v, o);
        if (lane == 0) sWsum[w] = v;
        __syncthreads();
        if (tid == 0) {
            float s = 0.f;
            #pragma unroll
            for (int i = 0; i < 8; i++) s += sWsum[i];
            out[0] = s;
        }
    }
}

// ---------------------------------------------------------------------------
extern "C" void kernel_launch(void* const* d_in, const int* in_sizes, int n_in,
                              void* d_out, int out_size) {
    const float* verts = nullptr;
    const float* tex   = nullptr;
    const float* ref   = nullptr;
    const int*   faces = nullptr;
    for (int i = 0; i < n_in; i++) {
        switch (in_sizes[i]) {
            case 1926:   verts = (const float*)d_in[i]; break;
            case 98304:  tex   = (const float*)d_in[i]; break;
            case 196608: ref   = (const float*)d_in[i]; break;
            case 1536:   faces = (const int*)  d_in[i]; break;
            default: break;
        }
    }
    prep_and_tanh<<<98, 256>>>(verts, faces, tex);
    raster<<<RBLK, RTPB>>>(ref, (float*)d_out);
}

// round 4
// speedup vs baseline: 1.7372x; 1.0298x over previous
#include <cuda_runtime.h>
#include <math.h>

#define NFACES 512
#define HW     256
#define NPIX   (HW*HW)
#define NTEX   (NFACES*64*3)      // 98304
#define TILE   8
#define TPD    32                 // tiles per dimension
#define RBLK   (TPD*TPD)          // 1024 blocks
#define RTPB   256                // 8 warps: 4 face-groups x 64 px

__device__ float4 g_bbox[NFACES];
__device__ float4 g_face[NFACES*4];       // q0,q1,q2,(r,-,-,-)
__device__ float  g_tanhTex[NTEX];
__device__ float  g_partials[RBLK];
__device__ unsigned int g_counter;

// ---------------------------------------------------------------------------
// Kernel A: fused per-face prep (blocks 0-1) + texture tanh (blocks 2..97)
// ---------------------------------------------------------------------------
__global__ void __launch_bounds__(256) prep_and_tanh(const float* __restrict__ verts,
                                                     const int*   __restrict__ faces,
                                                     const float* __restrict__ tex) {
    int b = blockIdx.x;
    if (b >= 2) {
        int i = (b - 2) * 256 + threadIdx.x;
        float4 v = __ldg(reinterpret_cast<const float4*>(tex) + i);
        v.x = tanhf(v.x); v.y = tanhf(v.y); v.z = tanhf(v.z); v.w = tanhf(v.w);
        reinterpret_cast<float4*>(g_tanhTex)[i] = v;
        return;
    }
    if (b == 0 && threadIdx.x == 0) g_counter = 0;

    int f = b * 256 + threadIdx.x;

    const float ex = 2.732f, ey = 0.0f, ez = -1.6728675276352844e-16f;
    float n  = sqrtf(ex*ex + ey*ey + ez*ez);
    float zx = -ex/n, zy = -ey/n, zz = -ez/n;
    float xx = zz, xy = 0.f, xz = -zx;
    float xn = sqrtf(xx*xx + xy*xy + xz*xz);
    xx /= xn; xy /= xn; xz /= xn;
    float yx = zy*xz - zz*xy;
    float yy = zz*xx - zx*xz;
    float yz = zx*xy - zy*xx;

    int i0 = faces[3*f+0], i1 = faces[3*f+1], i2 = faces[3*f+2];

    float vx, vy, vz;
    vx = verts[3*i0+0]-ex; vy = verts[3*i0+1]-ey; vz = verts[3*i0+2]-ez;
    float ax = vx*xx+vy*xy+vz*xz, ay = vx*yx+vy*yy+vz*yz, az = vx*zx+vy*zy+vz*zz;
    vx = verts[3*i1+0]-ex; vy = verts[3*i1+1]-ey; vz = verts[3*i1+2]-ez;
    float bx = vx*xx+vy*xy+vz*xz, by = vx*yx+vy*yy+vz*yz, bz = vx*zx+vy*zy+vz*zz;
    vx = verts[3*i2+0]-ex; vy = verts[3*i2+1]-ey; vz = verts[3*i2+2]-ez;
    float cx = vx*xx+vy*xy+vz*xz, cy = vx*yx+vy*yy+vz*yz, cz = vx*zx+vy*zy+vz*zz;

    float denom = (bx-ax)*(cy-ay) - (by-ay)*(cx-ax);
    float o[13];
    float4 bbox;
    if (fabsf(denom) <= 1e-8f) {
        #pragma unroll
        for (int k = 0; k < 13; k++) o[k] = 0.f;
        o[2] = -1.f; o[5] = -1.f; o[8] = -1.f;
        bbox = make_float4(2.f, -2.f, 2.f, -2.f);   // empty -> always culled
    } else {
        float s = (denom > 0.f) ? 1.f : -1.f;
        float r = 1.0f / fabsf(denom);
        o[0] = s*(by-cy);                      // A0
        o[1] = s*(cx-bx);                      // B0
        o[2] = s*((cy-by)*bx - (cx-bx)*by);    // C0
        o[3] = s*(cy-ay);                      // A1
        o[4] = s*(ax-cx);                      // B1
        o[5] = s*((ay-cy)*cx - (ax-cx)*cy);    // C1
        o[6] = s*(ay-by);                      // A2
        o[7] = s*(bx-ax);                      // B2
        o[8] = s*((by-ay)*ax - (bx-ax)*ay);    // C2
        float D0 = az*r, D1 = bz*r, D2 = cz*r;
        o[9]  = o[0]*D0 + o[3]*D1 + o[6]*D2;   // Dx
        o[10] = o[1]*D0 + o[4]*D1 + o[7]*D2;   // Dy
        o[11] = o[2]*D0 + o[5]*D1 + o[8]*D2;   // Dc
        o[12] = r;
        float xmn = fminf(ax, fminf(bx, cx)) - 1e-6f;
        float xmx = fmaxf(ax, fmaxf(bx, cx)) + 1e-6f;
        float ymn = fminf(ay, fminf(by, cy)) - 1e-6f;
        float ymx = fmaxf(ay, fmaxf(by, cy)) + 1e-6f;
        bbox = make_float4(xmn, xmx, ymn, ymx);
    }
    g_bbox[f] = bbox;
    float4* dst = &g_face[f*4];
    dst[0] = make_float4(o[0], o[1], o[2],  o[3]);   // A0 B0 C0 A1
    dst[1] = make_float4(o[4], o[5], o[6],  o[7]);   // B1 C1 A2 B2
    dst[2] = make_float4(o[8], o[9], o[10], o[11]);  // C2 Dx Dy Dc
    dst[3] = make_float4(o[12], 0.f, 0.f, 0.f);      // r
}

// ---------------------------------------------------------------------------
// Kernel B: 8x8-tile raster, 4-way face split, fused deterministic finalize
// ---------------------------------------------------------------------------
__global__ void __launch_bounds__(RTPB) raster(const float* __restrict__ ref,
                                               float* __restrict__ out) {
    __shared__ float4 sQ[NFACES*3];        // 24 KB survivor coefficients
    __shared__ short  sList[NFACES];       // survivor -> face id
    __shared__ int    sWarpCnt[8];
    __shared__ int    sCnt;
    __shared__ float  sBd[4][64];
    __shared__ short  sLi[4][64];
    __shared__ float  sWsum[8];

    const int tid  = threadIdx.x;
    const int lane = tid & 31, w = tid >> 5;

    const int tileX = blockIdx.x & (TPD-1), tileY = blockIdx.x / TPD;
    const int c0 = tileX * TILE, r0 = tileY * TILE;
    const float SC = 2.0f / 256.0f;
    const float tXmin = (c0 + 0.5f) * SC - 1.0f;
    const float tXmax = (c0 + TILE - 0.5f) * SC - 1.0f;
    const float tYmax = 1.0f - (r0 + 0.5f) * SC;
    const float tYmin = 1.0f - (r0 + TILE - 0.5f) * SC;

    if (tid == 0) sCnt = 0;
    __syncthreads();

    // ---- Phase 1: bbox cull + ballot compaction (2 rounds of 256) ----
    #pragma unroll
    for (int base = 0; base < NFACES; base += RTPB) {
        int f = base + tid;
        float4 bb = __ldg(&g_bbox[f]);
        bool ov = (bb.x <= tXmax) & (bb.y >= tXmin) & (bb.z <= tYmax) & (bb.w >= tYmin);
        unsigned m = __ballot_sync(0xFFFFFFFFu, ov);
        if (lane == 0) sWarpCnt[w] = __popc(m);
        __syncthreads();
        int off = sCnt;
        #pragma unroll
        for (int i = 0; i < 8; i++) if (i < w) off += sWarpCnt[i];
        if (ov) sList[off + __popc(m & ((1u << lane) - 1u))] = (short)f;
        __syncthreads();
        if (tid == 0) {
            int s = 0;
            #pragma unroll
            for (int i = 0; i < 8; i++) s += sWarpCnt[i];
            sCnt += s;
        }
        __syncthreads();
    }
    const int nf = sCnt;

    // ---- Stage survivor coefficients ----
    for (int i = tid; i < nf * 3; i += RTPB) {
        int li = i / 3, c = i - li * 3;
        sQ[i] = __ldg(&g_face[(int)sList[li] * 4 + c]);
    }
    __syncthreads();

    // ---- Phase 2: 4 groups of 64 threads; group g scans quarter g ----
    const int group = tid >> 6;
    const int sub   = tid & 63;                   // pixel slot within tile
    const float px = (c0 + (sub & 7) + 0.5f) * SC - 1.0f;
    const float py = 1.0f - (r0 + (sub >> 3) + 0.5f) * SC;

    const int fBeg = (nf * group)     >> 2;
    const int fEnd = (nf * (group+1)) >> 2;

    float bd = __int_as_float(0x7f800000);
    int   li = -1;

    #pragma unroll 4
    for (int i = fBeg; i < fEnd; i++) {
        float4 q0 = sQ[i*3+0];
        float4 q1 = sQ[i*3+1];
        float4 q2 = sQ[i*3+2];
        float u0 = fmaf(q0.x, px, fmaf(q0.y, py, q0.z));
        float u1 = fmaf(q0.w, px, fmaf(q1.x, py, q1.y));
        float u2 = fmaf(q1.z, px, fmaf(q1.w, py, q2.x));
        float d  = fmaf(q2.y, px, fmaf(q2.z, py, q2.w));
        float m  = fminf(u0, fminf(u1, u2));
        if (m >= 0.f && d > 0.f && d < bd) { bd = d; li = i; }
    }
    sBd[group][sub] = bd;
    sLi[group][sub] = (short)li;
    __syncthreads();

    // ---- Epilogue: 64 threads merge candidates (ascending group = argmin) --
    float acc = 0.f;
    if (tid < 64) {
        float best = sBd[0][tid];
        int   bli  = sLi[0][tid];
        #pragma unroll
        for (int g = 1; g < 4; g++) {
            float dg = sBd[g][tid];
            if (dg < best) { best = dg; bli = sLi[g][tid]; }
        }
        const float qx = (c0 + (tid & 7) + 0.5f) * SC - 1.0f;
        const float qy = 1.0f - (r0 + (tid >> 3) + 0.5f) * SC;
        const int   p  = (r0 + (tid >> 3)) * HW + (c0 + (tid & 7));

        float cc0 = 0.f, cc1 = 0.f, cc2 = 0.f;
        if (bli >= 0) {
            int f = sList[bli];
            float4 q0 = sQ[bli*3+0];
            float4 q1 = sQ[bli*3+1];
            float  C2 = sQ[bli*3+2].x;
            float  r  = __ldg(&g_face[f*4+3]).x;
            float u0 = fmaf(q0.x, qx, fmaf(q0.y, qy, q0.z));
            float u1 = fmaf(q0.w, qx, fmaf(q1.x, qy, q1.y));
            float u2 = fmaf(q1.z, qx, fmaf(q1.w, qy, C2));
            int t0 = min(max((int)rintf(u0 * r * 3.0f), 0), 3);
            int t1 = min(max((int)rintf(u1 * r * 3.0f), 0), 3);
            int t2 = min(max((int)rintf(u2 * r * 3.0f), 0), 3);
            int base = f*192 + t0*48 + t1*12 + t2*3;
            cc0 = g_tanhTex[base+0];
            cc1 = g_tanhTex[base+1];
            cc2 = g_tanhTex[base+2];
        }
        float e0 = cc0 - __ldg(ref + p);
        float e1 = cc1 - __ldg(ref + p + NPIX);
        float e2 = cc2 - __ldg(ref + p + 2*NPIX);
        acc = fmaf(e0, e0, fmaf(e1, e1, e2*e2));
    }

    // ---- block reduction (8 warps; only warps 0-1 contribute nonzero) ----
    #pragma unroll
    for (int o = 16; o > 0; o >>= 1)
        acc += __shfl_down_sync(0xFFFFFFFFu, acc, o);
    if (lane == 0) sWsum[w] = acc;
    __syncthreads();

    // ---- fused deterministic finalize (last block, fixed summation order) --
    __shared__ bool sLast;
    if (tid == 0) {
        g_partials[blockIdx.x] = sWsum[0] + sWsum[1];
        __threadfence();
        unsigned t = atomicInc(&g_counter, 0xFFFFFFFFu);
        sLast = (t == RBLK - 1);
    }
    __syncthreads();
    if (sLast) {
        float v = __ldcg(&g_partials[tid])
                + __ldcg(&g_partials[tid + 256])
                + __ldcg(&g_partials[tid + 512])
                + __ldcg(&g_partials[tid + 768]);
        #pragma unroll
        for (int o = 16; o > 0; o >>= 1)
            v += __shfl_down_sync(0xFFFFFFFFu, v, o);
        if (lane == 0) sWsum[w] = v;
        __syncthreads();
        if (tid == 0) {
            float s = 0.f;
            #pragma unroll
            for (int i = 0; i < 8; i++) s += sWsum[i];
            out[0] = s;
        }
    }
}

// ---------------------------------------------------------------------------
extern "C" void kernel_launch(void* const* d_in, const int* in_sizes, int n_in,
                              void* d_out, int out_size) {
    const float* verts = nullptr;
    const float* tex   = nullptr;
    const float* ref   = nullptr;
    const int*   faces = nullptr;
    for (int i = 0; i < n_in; i++) {
        switch (in_sizes[i]) {
            case 1926:   verts = (const float*)d_in[i]; break;
            case 98304:  tex   = (const float*)d_in[i]; break;
            case 196608: ref   = (const float*)d_in[i]; break;
            case 1536:   faces = (const int*)  d_in[i]; break;
            default: break;
        }
    }
    prep_and_tanh<<<98, 256>>>(verts, faces, tex);
    raster<<<RBLK, RTPB>>>(ref, (float*)d_out);
}